// round 13
// baseline (speedup 1.0000x reference)
#include <cuda_runtime.h>

typedef unsigned long long u64;

#define NTOK      262144      // B*T = 32*8192
#define DD        8
#define QQ        8
#define KK        1024
#define KH        512         // codeword pairs per stage
#define TPB       128
#define TOKS      2           // tokens per thread
#define NCTA      (NTOK / (TPB * TOKS))   // 1024
#define QUANT_N   (NTOK * DD)             // 2097152
#define LOSS_IDX  QUANT_N
#define CODES_OFF (QUANT_N + 1)

__device__ float g_loss_partial[NCTA];
__device__ int   g_ctr = 0;

static __device__ __forceinline__ u64 pk2(float lo, float hi) {
    u64 r; asm("mov.b64 %0, {%1, %2};" : "=l"(r) : "f"(lo), "f"(hi)); return r;
}
static __device__ __forceinline__ void upk2(u64 v, float &lo, float &hi) {
    asm("mov.b64 {%0, %1}, %2;" : "=f"(lo), "=f"(hi) : "l"(v));
}
static __device__ __forceinline__ float lof(u64 v) {
    float lo, hi; asm("mov.b64 {%0, %1}, %2;" : "=f"(lo), "=f"(hi) : "l"(v)); return lo;
}
static __device__ __forceinline__ u64 ffma2(u64 a, u64 b, u64 c) {
    u64 d; asm("fma.rn.f32x2 %0, %1, %2, %3;" : "=l"(d) : "l"(a), "l"(b), "l"(c)); return d;
}
static __device__ __forceinline__ u64 fmul2(u64 a, u64 b) {
    u64 d; asm("mul.rn.f32x2 %0, %1, %2;" : "=l"(d) : "l"(a), "l"(b)); return d;
}
static __device__ __forceinline__ u64 fadd2(u64 a, u64 b) {
    u64 d; asm("add.rn.f32x2 %0, %1, %2;" : "=l"(d) : "l"(a), "l"(b)); return d;
}
// positive floats: signed-int compare == float compare; argmin on ALU pipe
static __device__ __forceinline__ void upk2i(u64 v, int &lo, int &hi) {
    asm("mov.b64 {%0, %1}, %2;" : "=r"(lo), "=r"(hi) : "l"(v));
}

// exact distance pair for codeword pair kk (must match the loop's op sequence
// bit-for-bit: fmul2 -> 7x ffma2 -> fadd2(A+B) -> fadd2(e'+ab)).
// m holds -2r packed; chain yields e' = -2*E_ref exactly (pow2 scaling is exact).
static __device__ __forceinline__ void dist_pair(const u64* __restrict__ s_cw,
                                                 const u64* __restrict__ s_c2,
                                                 int kk, const u64* m, u64 A2,
                                                 int &dl, int &dh)
{
    const u64* cw = s_cw + kk * DD;
    u64 e = fmul2(m[0], cw[0]);
    #pragma unroll
    for (int d = 1; d < DD; ++d) e = ffma2(m[d], cw[d], e);
    u64 ab = fadd2(A2, s_c2[kk]);
    u64 dd = fadd2(e, ab);
    upk2i(dd, dl, dh);
}

__global__ void __launch_bounds__(TPB, 6)
rvq_kernel(const float* __restrict__ x,
           const float* __restrict__ cbs,
           const float* __restrict__ ps,
           const float* __restrict__ pb,
           const float* __restrict__ convw,
           const float* __restrict__ convb,
           float* __restrict__ out)
{
    // codeword-pair-packed codebook: s_cw[p*8+d] = (c[2p][d], c[2p+1][d])
    __shared__ __align__(16) u64  s_cw[KH * DD];   // 32 KB
    __shared__ __align__(16) u64  s_c2[KH];        // 4 KB : (B_2p, B_2p+1)
    __shared__ float s_w[DD * DD];
    __shared__ float s_b[DD];
    __shared__ float s_ps[QQ];
    __shared__ float s_pb[QQ];
    __shared__ float s_red[TPB / 32];
    __shared__ int   s_last;

    const int tid = threadIdx.x;
    const int t0  = blockIdx.x * (TPB * TOKS) + tid;
    const int t1  = t0 + TPB;

    if (tid < DD * DD) s_w[tid] = convw[tid];
    if (tid < DD)      s_b[tid] = convb[tid];
    if (tid < QQ)      { s_ps[tid] = ps[tid]; s_pb[tid] = pb[tid]; }

    // residual state: m[d] = packed(-2*r_d, -2*r_d)  (exact pow2 scaling)
    u64 m0[DD], m1[DD];
    float A0, A1;     // |r|^2, square-then-sequential-add (reference order)
    {
        float4 a = *(const float4*)(x + (size_t)t0 * DD);
        float4 b = *(const float4*)(x + (size_t)t0 * DD + 4);
        float4 c = *(const float4*)(x + (size_t)t1 * DD);
        float4 d = *(const float4*)(x + (size_t)t1 * DD + 4);
        float r0[DD] = {a.x, a.y, a.z, a.w, b.x, b.y, b.z, b.w};
        float r1[DD] = {c.x, c.y, c.z, c.w, d.x, d.y, d.z, d.w};
        A0 = r0[0] * r0[0];
        A1 = r1[0] * r1[0];
        #pragma unroll
        for (int d2 = 1; d2 < DD; ++d2) {
            A0 = A0 + r0[d2] * r0[d2];
            A1 = A1 + r1[d2] * r1[d2];
        }
        #pragma unroll
        for (int d2 = 0; d2 < DD; ++d2) {
            float v0 = -2.0f * r0[d2];
            float v1 = -2.0f * r1[d2];
            m0[d2] = pk2(v0, v0);
            m1[d2] = pk2(v1, v1);
        }
    }

    float ls = 0.0f;
    const int  INFB  = 0x7f800000;

    for (int q = 0; q < QQ; ++q) {
        __syncthreads();   // protect previous stage's s_cw reads

        // ---- stage codebook into packed smem ----
        const float* cb = cbs + (size_t)q * KK * DD;
        for (int p = tid; p < KH; p += TPB) {
            const float4* cp = (const float4*)(cb + (size_t)p * 16);
            float4 u0 = cp[0], u1 = cp[1];   // codeword 2p
            float4 v0 = cp[2], v1 = cp[3];   // codeword 2p+1
            float c0[DD] = {u0.x, u0.y, u0.z, u0.w, u1.x, u1.y, u1.z, u1.w};
            float c1[DD] = {v0.x, v0.y, v0.z, v0.w, v1.x, v1.y, v1.z, v1.w};
            // B_k = (cb**2).sum(-1): round each square, then sequential add
            float n0 = c0[0] * c0[0];
            float n1 = c1[0] * c1[0];
            #pragma unroll
            for (int d = 1; d < DD; ++d) {
                n0 = n0 + c0[d] * c0[d];
                n1 = n1 + c1[d] * c1[d];
            }
            #pragma unroll
            for (int d = 0; d < DD; ++d)
                s_cw[p * DD + d] = pk2(c0[d], c1[d]);
            s_c2[p] = pk2(n0, n1);
        }
        __syncthreads();

        // ---- 1024-way argmin: ONE min-chain per token over min(dl,dh);
        //      even/odd resolution deferred to an exact recompute ----
        int b0 = INFB, b1 = INFB, k0 = 0, k1 = 0;
        const u64 A2_0 = pk2(A0, A0);
        const u64 A2_1 = pk2(A1, A1);

        #pragma unroll 4
        for (int kk = 0; kk < KH; ++kk) {
            ulonglong2 wa = *(const ulonglong2*)(s_cw + kk * DD + 0);
            ulonglong2 wb = *(const ulonglong2*)(s_cw + kk * DD + 2);
            ulonglong2 wc = *(const ulonglong2*)(s_cw + kk * DD + 4);
            ulonglong2 wd = *(const ulonglong2*)(s_cw + kk * DD + 6);

            u64 e0 = fmul2(m0[0], wa.x);         // = -2*fl(r0*c0) exactly
            u64 e1 = fmul2(m1[0], wa.x);
            e0 = ffma2(m0[1], wa.y, e0);  e1 = ffma2(m1[1], wa.y, e1);
            e0 = ffma2(m0[2], wb.x, e0);  e1 = ffma2(m1[2], wb.x, e1);
            e0 = ffma2(m0[3], wb.y, e0);  e1 = ffma2(m1[3], wb.y, e1);
            e0 = ffma2(m0[4], wc.x, e0);  e1 = ffma2(m1[4], wc.x, e1);
            e0 = ffma2(m0[5], wc.y, e0);  e1 = ffma2(m1[5], wc.y, e1);
            e0 = ffma2(m0[6], wd.x, e0);  e1 = ffma2(m1[6], wd.x, e1);
            e0 = ffma2(m0[7], wd.y, e0);  e1 = ffma2(m1[7], wd.y, e1);
            // e = -2*E_ref bit-exactly (pow2 scaling commutes with rounding)

            u64 c2 = s_c2[kk];
            u64 ab0 = fadd2(A2_0, c2);           // fl(A + B)
            u64 ab1 = fadd2(A2_1, c2);
            u64 d0 = fadd2(e0, ab0);             // fl((A+B) - 2E)
            u64 d1 = fadd2(e1, ab1);

            int dl0, dh0, dl1, dh1;
            upk2i(d0, dl0, dh0);
            upk2i(d1, dl1, dh1);
            int v0 = min(dl0, dh0);              // IMNMX (bit-exact fp min, >0)
            int v1 = min(dl1, dh1);
            k0 = (v0 < b0) ? kk : k0;   b0 = min(b0, v0);   // strict < : first pair
            k1 = (v1 < b1) ? kk : k1;   b1 = min(b1, v1);
        }

        // deferred even/odd resolution: recompute winner pair's distances with
        // the identical op sequence (same bits); tie (dl==dh) -> even (lower idx)
        int i0, i1;
        {
            int dl, dh;
            dist_pair(s_cw, s_c2, k0, m0, A2_0, dl, dh);
            i0 = (dl <= dh) ? 2 * k0 : 2 * k0 + 1;
            dist_pair(s_cw, s_c2, k1, m1, A2_1, dl, dh);
            i1 = (dl <= dh) ? 2 * k1 : 2 * k1 + 1;
        }

        // ---- residual + loss updates, reference rounding order ----
        {
            int p = i0 >> 1, hi = i0 & 1;
            float newA = 0.0f;
            #pragma unroll
            for (int d = 0; d < DD; ++d) {
                float clo, chi; upk2(s_cw[p * DD + d], clo, chi);
                float c = hi ? chi : clo;
                float r = -0.5f * lof(m0[d]);    // exact recovery
                float rn = r - c;                // new_res
                float t  = rn - c;               // sg(new_res) - embeds
                ls = fmaf(t, t, ls);
                float sqr = rn * rn;
                newA = (d == 0) ? sqr : (newA + sqr);
                float v = -2.0f * rn;            // exact
                m0[d] = pk2(v, v);
            }
            A0 = newA;
        }
        {
            int p = i1 >> 1, hi = i1 & 1;
            float newA = 0.0f;
            #pragma unroll
            for (int d = 0; d < DD; ++d) {
                float clo, chi; upk2(s_cw[p * DD + d], clo, chi);
                float c = hi ? chi : clo;
                float r = -0.5f * lof(m1[d]);
                float rn = r - c;
                float t  = rn - c;
                ls = fmaf(t, t, ls);
                float sqr = rn * rn;
                newA = (d == 0) ? sqr : (newA + sqr);
                float v = -2.0f * rn;
                m1[d] = pk2(v, v);
            }
            A1 = newA;
        }

        out[CODES_OFF + (size_t)q * NTOK + t0] = (float)i0;
        out[CODES_OFF + (size_t)q * NTOK + t1] = (float)i1;
    }

    // ---- epilogue: rebuild qsum from codes (re-read own writes), then conv ----
    {
        float qs0[DD], qs1[DD];
        #pragma unroll
        for (int d = 0; d < DD; ++d) { qs0[d] = 0.0f; qs1[d] = 0.0f; }

        #pragma unroll
        for (int q = 0; q < QQ; ++q) {
            int c0i = (int)out[CODES_OFF + (size_t)q * NTOK + t0];
            int c1i = (int)out[CODES_OFF + (size_t)q * NTOK + t1];
            const float4* g0 = (const float4*)(cbs + ((size_t)q * KK + c0i) * DD);
            const float4* g1 = (const float4*)(cbs + ((size_t)q * KK + c1i) * DD);
            float4 a0 = g0[0], b0v = g0[1];
            float4 a1 = g1[0], b1v = g1[1];
            float c0[DD] = {a0.x, a0.y, a0.z, a0.w, b0v.x, b0v.y, b0v.z, b0v.w};
            float c1[DD] = {a1.x, a1.y, a1.z, a1.w, b1v.x, b1v.y, b1v.z, b1v.w};
            float sq = s_ps[q], bq = s_pb[q];
            #pragma unroll
            for (int d = 0; d < DD; ++d) {
                qs0[d] = (qs0[d] + c0[d] * sq) + bq;   // reference op order
                qs1[d] = (qs1[d] + c1[d] * sq) + bq;
            }
        }

        float o0[DD], o1[DD];
        #pragma unroll
        for (int e = 0; e < DD; ++e) {
            float a0 = qs0[0] * s_w[e * DD];
            float a1 = qs1[0] * s_w[e * DD];
            #pragma unroll
            for (int d = 1; d < DD; ++d) {
                a0 = fmaf(qs0[d], s_w[e * DD + d], a0);
                a1 = fmaf(qs1[d], s_w[e * DD + d], a1);
            }
            o0[e] = a0 + s_b[e];
            o1[e] = a1 + s_b[e];
        }
        *(float4*)(out + (size_t)t0 * DD)     = make_float4(o0[0], o0[1], o0[2], o0[3]);
        *(float4*)(out + (size_t)t0 * DD + 4) = make_float4(o0[4], o0[5], o0[6], o0[7]);
        *(float4*)(out + (size_t)t1 * DD)     = make_float4(o1[0], o1[1], o1[2], o1[3]);
        *(float4*)(out + (size_t)t1 * DD + 4) = make_float4(o1[4], o1[5], o1[6], o1[7]);
    }

    // ---- deterministic per-CTA loss partial ----
    #pragma unroll
    for (int off = 16; off > 0; off >>= 1)
        ls += __shfl_down_sync(0xffffffffu, ls, off);
    if ((tid & 31) == 0) s_red[tid >> 5] = ls;
    __syncthreads();
    if (tid == 0) {
        g_loss_partial[blockIdx.x] = (s_red[0] + s_red[1]) + (s_red[2] + s_red[3]);
        __threadfence();
        int old = atomicAdd(&g_ctr, 1);
        s_last = (old == NCTA - 1) ? 1 : 0;
    }
    __syncthreads();

    // ---- last CTA: fixed-order global loss reduction (deterministic) ----
    if (s_last) {
        __threadfence();
        float v = 0.0f;
        #pragma unroll
        for (int j = 0; j < NCTA / TPB; ++j)
            v += g_loss_partial[tid + j * TPB];
        #pragma unroll
        for (int off = 16; off > 0; off >>= 1)
            v += __shfl_down_sync(0xffffffffu, v, off);
        if ((tid & 31) == 0) s_red[tid >> 5] = v;
        __syncthreads();
        if (tid == 0) {
            float tot = (s_red[0] + s_red[1]) + (s_red[2] + s_red[3]);
            out[LOSS_IDX] = tot * (0.25f / 2097152.0f);  // * COMMITMENT_COST / (B*T*D)
            g_ctr = 0;
        }
    }
}

extern "C" void kernel_launch(void* const* d_in, const int* in_sizes, int n_in,
                              void* d_out, int out_size)
{
    const float* x     = (const float*)d_in[0];
    const float* cbs   = (const float*)d_in[1];
    const float* psc   = (const float*)d_in[2];
    const float* pbs   = (const float*)d_in[3];
    const float* convw = (const float*)d_in[4];
    const float* convb = (const float*)d_in[5];
    float* out = (float*)d_out;

    rvq_kernel<<<NCTA, TPB>>>(x, cbs, psc, pbs, convw, convb, out);
}

// round 14
// speedup vs baseline: 1.0600x; 1.0600x over previous
#include <cuda_runtime.h>

typedef unsigned long long u64;

#define NTOK      262144      // B*T = 32*8192
#define DD        8
#define QQ        8
#define KK        1024
#define KHH       256         // codeword pairs per staged half
#define TPB       128
#define TOKS      2           // tokens per thread
#define NCTA      (NTOK / (TPB * TOKS))   // 1024
#define QUANT_N   (NTOK * DD)             // 2097152
#define LOSS_IDX  QUANT_N
#define CODES_OFF (QUANT_N + 1)

__device__ float g_loss_partial[NCTA];
__device__ int   g_ctr = 0;

static __device__ __forceinline__ u64 pk2(float lo, float hi) {
    u64 r; asm("mov.b64 %0, {%1, %2};" : "=l"(r) : "f"(lo), "f"(hi)); return r;
}
static __device__ __forceinline__ float lof(u64 v) {
    float lo, hi; asm("mov.b64 {%0, %1}, %2;" : "=f"(lo), "=f"(hi) : "l"(v)); return lo;
}
static __device__ __forceinline__ u64 ffma2(u64 a, u64 b, u64 c) {
    u64 d; asm("fma.rn.f32x2 %0, %1, %2, %3;" : "=l"(d) : "l"(a), "l"(b), "l"(c)); return d;
}
static __device__ __forceinline__ u64 fmul2(u64 a, u64 b) {
    u64 d; asm("mul.rn.f32x2 %0, %1, %2;" : "=l"(d) : "l"(a), "l"(b)); return d;
}
static __device__ __forceinline__ u64 fadd2(u64 a, u64 b) {
    u64 d; asm("add.rn.f32x2 %0, %1, %2;" : "=l"(d) : "l"(a), "l"(b)); return d;
}
// positive floats: signed-int compare == float compare; argmin on ALU pipe
static __device__ __forceinline__ void upk2i(u64 v, int &lo, int &hi) {
    asm("mov.b64 {%0, %1}, %2;" : "=r"(lo), "=r"(hi) : "l"(v));
}

__global__ void __launch_bounds__(TPB, 6)
rvq_kernel(const float* __restrict__ x,
           const float* __restrict__ cbs,
           const float* __restrict__ ps,
           const float* __restrict__ pb,
           const float* __restrict__ convw,
           const float* __restrict__ convb,
           float* __restrict__ out)
{
    // HALF codebook staged at a time: s_cw[p*8+d] = (c[2p][d], c[2p+1][d])
    __shared__ __align__(16) u64  s_cw[KHH * DD];  // 16 KB
    __shared__ __align__(16) u64  s_c2[KHH];       // 2 KB : (B_2p, B_2p+1)
    __shared__ float s_w[DD * DD];
    __shared__ float s_b[DD];
    __shared__ float s_ps[QQ];
    __shared__ float s_pb[QQ];
    __shared__ float s_red[TPB / 32];
    __shared__ int   s_last;

    const int tid = threadIdx.x;
    const int t0  = blockIdx.x * (TPB * TOKS) + tid;
    const int t1  = t0 + TPB;

    if (tid < DD * DD) s_w[tid] = convw[tid];
    if (tid < DD)      s_b[tid] = convb[tid];
    if (tid < QQ)      { s_ps[tid] = ps[tid]; s_pb[tid] = pb[tid]; }

    // residual state: m[d] = packed(-2*r_d, -2*r_d)  (exact pow2 scaling)
    u64 m0[DD], m1[DD];
    float A0, A1;     // |r|^2, square-then-sequential-add (reference order)
    {
        float4 a = *(const float4*)(x + (size_t)t0 * DD);
        float4 b = *(const float4*)(x + (size_t)t0 * DD + 4);
        float4 c = *(const float4*)(x + (size_t)t1 * DD);
        float4 d = *(const float4*)(x + (size_t)t1 * DD + 4);
        float r0[DD] = {a.x, a.y, a.z, a.w, b.x, b.y, b.z, b.w};
        float r1[DD] = {c.x, c.y, c.z, c.w, d.x, d.y, d.z, d.w};
        A0 = r0[0] * r0[0];
        A1 = r1[0] * r1[0];
        #pragma unroll
        for (int d2 = 1; d2 < DD; ++d2) {
            A0 = A0 + r0[d2] * r0[d2];
            A1 = A1 + r1[d2] * r1[d2];
        }
        #pragma unroll
        for (int d2 = 0; d2 < DD; ++d2) {
            float v0 = -2.0f * r0[d2];
            float v1 = -2.0f * r1[d2];
            m0[d2] = pk2(v0, v0);
            m1[d2] = pk2(v1, v1);
        }
    }

    float ls = 0.0f;
    const int INFB = 0x7f800000;

    for (int q = 0; q < QQ; ++q) {
        // argmin state persists across the two staged halves
        int b0 = INFB, b1 = INFB, k0 = 0, k1 = 0;
        const u64 A2_0 = pk2(A0, A0);
        const u64 A2_1 = pk2(A1, A1);

        #pragma unroll 1
        for (int h = 0; h < 2; ++h) {
            __syncthreads();   // previous half's readers done

            // ---- stage this half into packed smem (2 pairs per thread) ----
            const float* cb = cbs + ((size_t)q * KK + (size_t)h * (2 * KHH)) * DD;
            #pragma unroll
            for (int pp = 0; pp < KHH / TPB; ++pp) {
                int p = pp * TPB + tid;
                const float4* cp = (const float4*)(cb + (size_t)p * 16);
                float4 u0 = cp[0], u1 = cp[1];   // codeword 2p
                float4 v0 = cp[2], v1 = cp[3];   // codeword 2p+1
                float c0[DD] = {u0.x, u0.y, u0.z, u0.w, u1.x, u1.y, u1.z, u1.w};
                float c1[DD] = {v0.x, v0.y, v0.z, v0.w, v1.x, v1.y, v1.z, v1.w};
                // B_k = (cb**2).sum(-1): round each square, then sequential add
                float n0 = c0[0] * c0[0];
                float n1 = c1[0] * c1[0];
                #pragma unroll
                for (int d = 1; d < DD; ++d) {
                    n0 = n0 + c0[d] * c0[d];
                    n1 = n1 + c1[d] * c1[d];
                }
                #pragma unroll
                for (int d = 0; d < DD; ++d)
                    s_cw[p * DD + d] = pk2(c0[d], c1[d]);
                s_c2[p] = pk2(n0, n1);
            }
            __syncthreads();

            const int kofs = h * KHH;

            // ---- argmin over this half (identical op sequence to R12) ----
            #pragma unroll 4
            for (int kk = 0; kk < KHH; ++kk) {
                ulonglong2 wa = *(const ulonglong2*)(s_cw + kk * DD + 0);
                ulonglong2 wb = *(const ulonglong2*)(s_cw + kk * DD + 2);
                ulonglong2 wc = *(const ulonglong2*)(s_cw + kk * DD + 4);
                ulonglong2 wd = *(const ulonglong2*)(s_cw + kk * DD + 6);

                u64 e0 = fmul2(m0[0], wa.x);         // = -2*fl(r0*c0) exactly
                u64 e1 = fmul2(m1[0], wa.x);
                e0 = ffma2(m0[1], wa.y, e0);  e1 = ffma2(m1[1], wa.y, e1);
                e0 = ffma2(m0[2], wb.x, e0);  e1 = ffma2(m1[2], wb.x, e1);
                e0 = ffma2(m0[3], wb.y, e0);  e1 = ffma2(m1[3], wb.y, e1);
                e0 = ffma2(m0[4], wc.x, e0);  e1 = ffma2(m1[4], wc.x, e1);
                e0 = ffma2(m0[5], wc.y, e0);  e1 = ffma2(m1[5], wc.y, e1);
                e0 = ffma2(m0[6], wd.x, e0);  e1 = ffma2(m1[6], wd.x, e1);
                e0 = ffma2(m0[7], wd.y, e0);  e1 = ffma2(m1[7], wd.y, e1);
                // e = -2*E_ref bit-exactly (pow2 scaling commutes with rounding)

                u64 c2 = s_c2[kk];
                u64 ab0 = fadd2(A2_0, c2);           // fl(A + B)
                u64 ab1 = fadd2(A2_1, c2);
                u64 d0 = fadd2(e0, ab0);             // fl((A+B) - 2E)
                u64 d1 = fadd2(e1, ab1);

                int dl0, dh0, dl1, dh1;
                upk2i(d0, dl0, dh0);
                upk2i(d1, dl1, dh1);
                int v0 = min(dl0, dh0);              // IMNMX (bit-exact fp min, >0)
                int v1 = min(dl1, dh1);
                int kp = kofs + kk;
                k0 = (v0 < b0) ? kp : k0;   b0 = min(b0, v0);   // strict <: first pair
                k1 = (v1 < b1) ? kp : k1;   b1 = min(b1, v1);
            }
        }

        const size_t cbase = (size_t)q * KK;

        // ---- per-token: re-gather winning pair from gmem (same bits as the
        //      smem copy), recompute norm+distance with identical op sequences,
        //      resolve even/odd, update residual + loss ----
        #pragma unroll
        for (int tkn = 0; tkn < 2; ++tkn) {
            int kwin = tkn ? k1 : k0;
            u64* m = tkn ? m1 : m0;
            u64 A2 = tkn ? A2_1 : A2_0;

            const float4* gp = (const float4*)(cbs + (cbase + 2 * (size_t)kwin) * DD);
            float4 u0 = gp[0], u1 = gp[1];   // codeword 2k
            float4 v0 = gp[2], v1 = gp[3];   // codeword 2k+1
            float c0[DD] = {u0.x, u0.y, u0.z, u0.w, u1.x, u1.y, u1.z, u1.w};
            float c1[DD] = {v0.x, v0.y, v0.z, v0.w, v1.x, v1.y, v1.z, v1.w};
            // norm recompute: identical sequence to staging
            float n0 = c0[0] * c0[0];
            float n1 = c1[0] * c1[0];
            #pragma unroll
            for (int d = 1; d < DD; ++d) {
                n0 = n0 + c0[d] * c0[d];
                n1 = n1 + c1[d] * c1[d];
            }
            // distance recompute: identical sequence to the loop
            u64 e = fmul2(m[0], pk2(c0[0], c1[0]));
            #pragma unroll
            for (int d = 1; d < DD; ++d)
                e = ffma2(m[d], pk2(c0[d], c1[d]), e);
            u64 ab = fadd2(A2, pk2(n0, n1));
            u64 dd2 = fadd2(e, ab);
            int dl, dh;
            upk2i(dd2, dl, dh);
            int idx = (dl <= dh) ? 2 * kwin : 2 * kwin + 1;   // tie -> even (lower)
            int hi = idx & 1;

            float newA = 0.0f;
            #pragma unroll
            for (int d = 0; d < DD; ++d) {
                float c = hi ? c1[d] : c0[d];
                float r = -0.5f * lof(m[d]);     // exact recovery
                float rn = r - c;                // new_res (reference op)
                float tt = rn - c;               // sg(new_res) - embeds
                ls = fmaf(tt, tt, ls);
                float sqr = rn * rn;
                newA = (d == 0) ? sqr : (newA + sqr);
                float v = -2.0f * rn;            // exact
                m[d] = pk2(v, v);
            }
            if (tkn) A1 = newA; else A0 = newA;

            out[CODES_OFF + (size_t)q * NTOK + (tkn ? t1 : t0)] = (float)idx;
        }
    }

    // ---- epilogue: rebuild qsum from codes (re-read own writes), then conv ----
    {
        float qs0[DD], qs1[DD];
        #pragma unroll
        for (int d = 0; d < DD; ++d) { qs0[d] = 0.0f; qs1[d] = 0.0f; }

        #pragma unroll
        for (int q = 0; q < QQ; ++q) {
            int c0i = (int)out[CODES_OFF + (size_t)q * NTOK + t0];
            int c1i = (int)out[CODES_OFF + (size_t)q * NTOK + t1];
            const float4* g0 = (const float4*)(cbs + ((size_t)q * KK + c0i) * DD);
            const float4* g1 = (const float4*)(cbs + ((size_t)q * KK + c1i) * DD);
            float4 a0 = g0[0], b0v = g0[1];
            float4 a1 = g1[0], b1v = g1[1];
            float c0[DD] = {a0.x, a0.y, a0.z, a0.w, b0v.x, b0v.y, b0v.z, b0v.w};
            float c1[DD] = {a1.x, a1.y, a1.z, a1.w, b1v.x, b1v.y, b1v.z, b1v.w};
            float sq = s_ps[q], bq = s_pb[q];
            #pragma unroll
            for (int d = 0; d < DD; ++d) {
                qs0[d] = (qs0[d] + c0[d] * sq) + bq;   // reference op order
                qs1[d] = (qs1[d] + c1[d] * sq) + bq;
            }
        }

        float o0[DD], o1[DD];
        #pragma unroll
        for (int e = 0; e < DD; ++e) {
            float a0 = qs0[0] * s_w[e * DD];
            float a1 = qs1[0] * s_w[e * DD];
            #pragma unroll
            for (int d = 1; d < DD; ++d) {
                a0 = fmaf(qs0[d], s_w[e * DD + d], a0);
                a1 = fmaf(qs1[d], s_w[e * DD + d], a1);
            }
            o0[e] = a0 + s_b[e];
            o1[e] = a1 + s_b[e];
        }
        *(float4*)(out + (size_t)t0 * DD)     = make_float4(o0[0], o0[1], o0[2], o0[3]);
        *(float4*)(out + (size_t)t0 * DD + 4) = make_float4(o0[4], o0[5], o0[6], o0[7]);
        *(float4*)(out + (size_t)t1 * DD)     = make_float4(o1[0], o1[1], o1[2], o1[3]);
        *(float4*)(out + (size_t)t1 * DD + 4) = make_float4(o1[4], o1[5], o1[6], o1[7]);
    }

    // ---- deterministic per-CTA loss partial ----
    #pragma unroll
    for (int off = 16; off > 0; off >>= 1)
        ls += __shfl_down_sync(0xffffffffu, ls, off);
    if ((tid & 31) == 0) s_red[tid >> 5] = ls;
    __syncthreads();
    if (tid == 0) {
        g_loss_partial[blockIdx.x] = (s_red[0] + s_red[1]) + (s_red[2] + s_red[3]);
        __threadfence();
        int old = atomicAdd(&g_ctr, 1);
        s_last = (old == NCTA - 1) ? 1 : 0;
    }
    __syncthreads();

    // ---- last CTA: fixed-order global loss reduction (deterministic) ----
    if (s_last) {
        __threadfence();
        float v = 0.0f;
        #pragma unroll
        for (int j = 0; j < NCTA / TPB; ++j)
            v += g_loss_partial[tid + j * TPB];
        #pragma unroll
        for (int off = 16; off > 0; off >>= 1)
            v += __shfl_down_sync(0xffffffffu, v, off);
        if ((tid & 31) == 0) s_red[tid >> 5] = v;
        __syncthreads();
        if (tid == 0) {
            float tot = (s_red[0] + s_red[1]) + (s_red[2] + s_red[3]);
            out[LOSS_IDX] = tot * (0.25f / 2097152.0f);  // * COMMITMENT_COST / (B*T*D)
            g_ctr = 0;
        }
    }
}

extern "C" void kernel_launch(void* const* d_in, const int* in_sizes, int n_in,
                              void* d_out, int out_size)
{
    const float* x     = (const float*)d_in[0];
    const float* cbs   = (const float*)d_in[1];
    const float* psc   = (const float*)d_in[2];
    const float* pbs   = (const float*)d_in[3];
    const float* convw = (const float*)d_in[4];
    const float* convb = (const float*)d_in[5];
    float* out = (float*)d_out;

    rvq_kernel<<<NCTA, TPB>>>(x, cbs, psc, pbs, convw, convb, out);
}

// round 15
// speedup vs baseline: 1.0698x; 1.0093x over previous
#include <cuda_runtime.h>

typedef unsigned long long u64;

#define NTOK      262144      // B*T = 32*8192
#define DD        8
#define QQ        8
#define KK        1024
#define KHH       256         // codeword pairs per staged half
#define TPB       128
#define TOKS      2           // tokens per thread
#define NCTA      (NTOK / (TPB * TOKS))   // 1024
#define QUANT_N   (NTOK * DD)             // 2097152
#define LOSS_IDX  QUANT_N
#define CODES_OFF (QUANT_N + 1)

__device__ float g_loss_partial[NCTA];
__device__ int   g_ctr = 0;

static __device__ __forceinline__ u64 pk2(float lo, float hi) {
    u64 r; asm("mov.b64 %0, {%1, %2};" : "=l"(r) : "f"(lo), "f"(hi)); return r;
}
static __device__ __forceinline__ float lof(u64 v) {
    float lo, hi; asm("mov.b64 {%0, %1}, %2;" : "=f"(lo), "=f"(hi) : "l"(v)); return lo;
}
static __device__ __forceinline__ u64 ffma2(u64 a, u64 b, u64 c) {
    u64 d; asm("fma.rn.f32x2 %0, %1, %2, %3;" : "=l"(d) : "l"(a), "l"(b), "l"(c)); return d;
}
static __device__ __forceinline__ u64 fmul2(u64 a, u64 b) {
    u64 d; asm("mul.rn.f32x2 %0, %1, %2;" : "=l"(d) : "l"(a), "l"(b)); return d;
}
static __device__ __forceinline__ u64 fadd2(u64 a, u64 b) {
    u64 d; asm("add.rn.f32x2 %0, %1, %2;" : "=l"(d) : "l"(a), "l"(b)); return d;
}
// positive floats: signed-int compare == float compare; argmin on ALU pipe
static __device__ __forceinline__ void upk2i(u64 v, int &lo, int &hi) {
    asm("mov.b64 {%0, %1}, %2;" : "=r"(lo), "=r"(hi) : "l"(v));
}

__global__ void __launch_bounds__(TPB, 7)
rvq_kernel(const float* __restrict__ x,
           const float* __restrict__ cbs,
           const float* __restrict__ ps,
           const float* __restrict__ pb,
           const float* __restrict__ convw,
           const float* __restrict__ convb,
           float* __restrict__ out)
{
    // HALF codebook staged at a time: s_cw[p*8+d] = (c[2p][d], c[2p+1][d])
    __shared__ __align__(16) u64  s_cw[KHH * DD];  // 16 KB
    __shared__ __align__(16) u64  s_c2[KHH];       // 2 KB : (B_2p, B_2p+1)
    __shared__ float s_w[DD * DD];
    __shared__ float s_b[DD];
    __shared__ float s_ps[QQ];
    __shared__ float s_pb[QQ];
    __shared__ float s_red[TPB / 32];
    __shared__ int   s_last;

    const int tid = threadIdx.x;
    const int t0  = blockIdx.x * (TPB * TOKS) + tid;
    const int t1  = t0 + TPB;

    if (tid < DD * DD) s_w[tid] = convw[tid];
    if (tid < DD)      s_b[tid] = convb[tid];
    if (tid < QQ)      { s_ps[tid] = ps[tid]; s_pb[tid] = pb[tid]; }

    // residual state: m[d] = packed(-2*r_d, -2*r_d)  (exact pow2 scaling)
    u64 m0[DD], m1[DD];
    float A0, A1;     // |r|^2, square-then-sequential-add (reference order)
    {
        float4 a = *(const float4*)(x + (size_t)t0 * DD);
        float4 b = *(const float4*)(x + (size_t)t0 * DD + 4);
        float4 c = *(const float4*)(x + (size_t)t1 * DD);
        float4 d = *(const float4*)(x + (size_t)t1 * DD + 4);
        float r0[DD] = {a.x, a.y, a.z, a.w, b.x, b.y, b.z, b.w};
        float r1[DD] = {c.x, c.y, c.z, c.w, d.x, d.y, d.z, d.w};
        A0 = r0[0] * r0[0];
        A1 = r1[0] * r1[0];
        #pragma unroll
        for (int d2 = 1; d2 < DD; ++d2) {
            A0 = A0 + r0[d2] * r0[d2];
            A1 = A1 + r1[d2] * r1[d2];
        }
        #pragma unroll
        for (int d2 = 0; d2 < DD; ++d2) {
            float v0 = -2.0f * r0[d2];
            float v1 = -2.0f * r1[d2];
            m0[d2] = pk2(v0, v0);
            m1[d2] = pk2(v1, v1);
        }
    }

    float ls = 0.0f;
    const int INFB = 0x7f800000;

    for (int q = 0; q < QQ; ++q) {
        // argmin state persists across the two staged halves
        int b0 = INFB, b1 = INFB, k0 = 0, k1 = 0;
        const u64 A2_0 = pk2(A0, A0);
        const u64 A2_1 = pk2(A1, A1);

        #pragma unroll 1
        for (int h = 0; h < 2; ++h) {
            __syncthreads();   // previous half's readers done

            // ---- stage this half into packed smem (2 pairs per thread) ----
            const float* cb = cbs + ((size_t)q * KK + (size_t)h * (2 * KHH)) * DD;
            #pragma unroll
            for (int pp = 0; pp < KHH / TPB; ++pp) {
                int p = pp * TPB + tid;
                const float4* cp = (const float4*)(cb + (size_t)p * 16);
                float4 u0 = cp[0], u1 = cp[1];   // codeword 2p
                float4 v0 = cp[2], v1 = cp[3];   // codeword 2p+1
                float c0[DD] = {u0.x, u0.y, u0.z, u0.w, u1.x, u1.y, u1.z, u1.w};
                float c1[DD] = {v0.x, v0.y, v0.z, v0.w, v1.x, v1.y, v1.z, v1.w};
                // B_k = (cb**2).sum(-1): round each square, then sequential add
                float n0 = c0[0] * c0[0];
                float n1 = c1[0] * c1[0];
                #pragma unroll
                for (int d = 1; d < DD; ++d) {
                    n0 = n0 + c0[d] * c0[d];
                    n1 = n1 + c1[d] * c1[d];
                }
                #pragma unroll
                for (int d = 0; d < DD; ++d)
                    s_cw[p * DD + d] = pk2(c0[d], c1[d]);
                s_c2[p] = pk2(n0, n1);
            }
            __syncthreads();

            const int kofs = h * KHH;

            // ---- argmin over this half (identical op sequence to R12) ----
            #pragma unroll 4
            for (int kk = 0; kk < KHH; ++kk) {
                ulonglong2 wa = *(const ulonglong2*)(s_cw + kk * DD + 0);
                ulonglong2 wb = *(const ulonglong2*)(s_cw + kk * DD + 2);
                ulonglong2 wc = *(const ulonglong2*)(s_cw + kk * DD + 4);
                ulonglong2 wd = *(const ulonglong2*)(s_cw + kk * DD + 6);

                u64 e0 = fmul2(m0[0], wa.x);         // = -2*fl(r0*c0) exactly
                u64 e1 = fmul2(m1[0], wa.x);
                e0 = ffma2(m0[1], wa.y, e0);  e1 = ffma2(m1[1], wa.y, e1);
                e0 = ffma2(m0[2], wb.x, e0);  e1 = ffma2(m1[2], wb.x, e1);
                e0 = ffma2(m0[3], wb.y, e0);  e1 = ffma2(m1[3], wb.y, e1);
                e0 = ffma2(m0[4], wc.x, e0);  e1 = ffma2(m1[4], wc.x, e1);
                e0 = ffma2(m0[5], wc.y, e0);  e1 = ffma2(m1[5], wc.y, e1);
                e0 = ffma2(m0[6], wd.x, e0);  e1 = ffma2(m1[6], wd.x, e1);
                e0 = ffma2(m0[7], wd.y, e0);  e1 = ffma2(m1[7], wd.y, e1);
                // e = -2*E_ref bit-exactly (pow2 scaling commutes with rounding)

                u64 c2 = s_c2[kk];
                u64 ab0 = fadd2(A2_0, c2);           // fl(A + B)
                u64 ab1 = fadd2(A2_1, c2);
                u64 d0 = fadd2(e0, ab0);             // fl((A+B) - 2E)
                u64 d1 = fadd2(e1, ab1);

                int dl0, dh0, dl1, dh1;
                upk2i(d0, dl0, dh0);
                upk2i(d1, dl1, dh1);
                int v0 = min(dl0, dh0);              // IMNMX (bit-exact fp min, >0)
                int v1 = min(dl1, dh1);
                int kp = kofs + kk;
                k0 = (v0 < b0) ? kp : k0;   b0 = min(b0, v0);   // strict <: first pair
                k1 = (v1 < b1) ? kp : k1;   b1 = min(b1, v1);
            }
        }

        const size_t cbase = (size_t)q * KK;

        // ---- per-token: re-gather winning pair from gmem (same bits as the
        //      smem copy), recompute norm+distance with identical op sequences,
        //      resolve even/odd, update residual + loss ----
        #pragma unroll
        for (int tkn = 0; tkn < 2; ++tkn) {
            int kwin = tkn ? k1 : k0;
            u64* m = tkn ? m1 : m0;
            u64 A2 = tkn ? A2_1 : A2_0;

            const float4* gp = (const float4*)(cbs + (cbase + 2 * (size_t)kwin) * DD);
            float4 u0 = gp[0], u1 = gp[1];   // codeword 2k
            float4 v0 = gp[2], v1 = gp[3];   // codeword 2k+1
            float c0[DD] = {u0.x, u0.y, u0.z, u0.w, u1.x, u1.y, u1.z, u1.w};
            float c1[DD] = {v0.x, v0.y, v0.z, v0.w, v1.x, v1.y, v1.z, v1.w};
            // norm recompute: identical sequence to staging
            float n0 = c0[0] * c0[0];
            float n1 = c1[0] * c1[0];
            #pragma unroll
            for (int d = 1; d < DD; ++d) {
                n0 = n0 + c0[d] * c0[d];
                n1 = n1 + c1[d] * c1[d];
            }
            // distance recompute: identical sequence to the loop
            u64 e = fmul2(m[0], pk2(c0[0], c1[0]));
            #pragma unroll
            for (int d = 1; d < DD; ++d)
                e = ffma2(m[d], pk2(c0[d], c1[d]), e);
            u64 ab = fadd2(A2, pk2(n0, n1));
            u64 dd2 = fadd2(e, ab);
            int dl, dh;
            upk2i(dd2, dl, dh);
            int idx = (dl <= dh) ? 2 * kwin : 2 * kwin + 1;   // tie -> even (lower)
            int hi = idx & 1;

            float newA = 0.0f;
            #pragma unroll
            for (int d = 0; d < DD; ++d) {
                float c = hi ? c1[d] : c0[d];
                float r = -0.5f * lof(m[d]);     // exact recovery
                float rn = r - c;                // new_res (reference op)
                float tt = rn - c;               // sg(new_res) - embeds
                ls = fmaf(tt, tt, ls);
                float sqr = rn * rn;
                newA = (d == 0) ? sqr : (newA + sqr);
                float v = -2.0f * rn;            // exact
                m[d] = pk2(v, v);
            }
            if (tkn) A1 = newA; else A0 = newA;

            out[CODES_OFF + (size_t)q * NTOK + (tkn ? t1 : t0)] = (float)idx;
        }
    }

    // ---- epilogue: rebuild qsum from codes (re-read own writes), then conv ----
    {
        float qs0[DD], qs1[DD];
        #pragma unroll
        for (int d = 0; d < DD; ++d) { qs0[d] = 0.0f; qs1[d] = 0.0f; }

        #pragma unroll
        for (int q = 0; q < QQ; ++q) {
            int c0i = (int)out[CODES_OFF + (size_t)q * NTOK + t0];
            int c1i = (int)out[CODES_OFF + (size_t)q * NTOK + t1];
            const float4* g0 = (const float4*)(cbs + ((size_t)q * KK + c0i) * DD);
            const float4* g1 = (const float4*)(cbs + ((size_t)q * KK + c1i) * DD);
            float4 a0 = g0[0], b0v = g0[1];
            float4 a1 = g1[0], b1v = g1[1];
            float c0[DD] = {a0.x, a0.y, a0.z, a0.w, b0v.x, b0v.y, b0v.z, b0v.w};
            float c1[DD] = {a1.x, a1.y, a1.z, a1.w, b1v.x, b1v.y, b1v.z, b1v.w};
            float sq = s_ps[q], bq = s_pb[q];
            #pragma unroll
            for (int d = 0; d < DD; ++d) {
                qs0[d] = (qs0[d] + c0[d] * sq) + bq;   // reference op order
                qs1[d] = (qs1[d] + c1[d] * sq) + bq;
            }
        }

        float o0[DD], o1[DD];
        #pragma unroll
        for (int e = 0; e < DD; ++e) {
            float a0 = qs0[0] * s_w[e * DD];
            float a1 = qs1[0] * s_w[e * DD];
            #pragma unroll
            for (int d = 1; d < DD; ++d) {
                a0 = fmaf(qs0[d], s_w[e * DD + d], a0);
                a1 = fmaf(qs1[d], s_w[e * DD + d], a1);
            }
            o0[e] = a0 + s_b[e];
            o1[e] = a1 + s_b[e];
        }
        *(float4*)(out + (size_t)t0 * DD)     = make_float4(o0[0], o0[1], o0[2], o0[3]);
        *(float4*)(out + (size_t)t0 * DD + 4) = make_float4(o0[4], o0[5], o0[6], o0[7]);
        *(float4*)(out + (size_t)t1 * DD)     = make_float4(o1[0], o1[1], o1[2], o1[3]);
        *(float4*)(out + (size_t)t1 * DD + 4) = make_float4(o1[4], o1[5], o1[6], o1[7]);
    }

    // ---- deterministic per-CTA loss partial ----
    #pragma unroll
    for (int off = 16; off > 0; off >>= 1)
        ls += __shfl_down_sync(0xffffffffu, ls, off);
    if ((tid & 31) == 0) s_red[tid >> 5] = ls;
    __syncthreads();
    if (tid == 0) {
        g_loss_partial[blockIdx.x] = (s_red[0] + s_red[1]) + (s_red[2] + s_red[3]);
        __threadfence();
        int old = atomicAdd(&g_ctr, 1);
        s_last = (old == NCTA - 1) ? 1 : 0;
    }
    __syncthreads();

    // ---- last CTA: fixed-order global loss reduction (deterministic) ----
    if (s_last) {
        __threadfence();
        float v = 0.0f;
        #pragma unroll
        for (int j = 0; j < NCTA / TPB; ++j)
            v += g_loss_partial[tid + j * TPB];
        #pragma unroll
        for (int off = 16; off > 0; off >>= 1)
            v += __shfl_down_sync(0xffffffffu, v, off);
        if ((tid & 31) == 0) s_red[tid >> 5] = v;
        __syncthreads();
        if (tid == 0) {
            float tot = (s_red[0] + s_red[1]) + (s_red[2] + s_red[3]);
            out[LOSS_IDX] = tot * (0.25f / 2097152.0f);  // * COMMITMENT_COST / (B*T*D)
            g_ctr = 0;
        }
    }
}

extern "C" void kernel_launch(void* const* d_in, const int* in_sizes, int n_in,
                              void* d_out, int out_size)
{
    const float* x     = (const float*)d_in[0];
    const float* cbs   = (const float*)d_in[1];
    const float* psc   = (const float*)d_in[2];
    const float* pbs   = (const float*)d_in[3];
    const float* convw = (const float*)d_in[4];
    const float* convb = (const float*)d_in[5];
    float* out = (float*)d_out;

    rvq_kernel<<<NCTA, TPB>>>(x, cbs, psc, pbs, convw, convb, out);
}